// round 12
// baseline (speedup 1.0000x reference)
#include <cuda_runtime.h>
#include <cuda_bf16.h>

#define Bn   8
#define Cn   256
#define Gn   32
#define CPG  8
#define Hn   56
#define Wn   56
#define HWn  3136        // 56*56
#define QW   14          // float4 quads per row
#define ROWS 4           // output rows per block
#define BTH  (QW*CPG*ROWS)       // 448 threads
#define NBLK (Bn*Gn*(Hn/ROWS))   // 3584
#define JSTR 340         // smem channel stride (6*56=336, padded, 16B-aligned)

__global__ __launch_bounds__(BTH, 2)
void SKA_20950850470021_kernel(const float* __restrict__ x,
                               const float* __restrict__ w,
                               float* __restrict__ out) {
    __shared__ float sx[CPG * JSTR];   // 8 ch x (6 rows x 56), zero-filled halo

    const int tid = threadIdx.x;
    const int bid = blockIdx.x;
    const int ht = bid % (Hn / ROWS);
    const int g  = (bid / (Hn / ROWS)) % Gn;
    const int b  = bid / ((Hn / ROWS) * Gn);
    const int h0 = ht * ROWS;

    // q innermost -> LDS/STG coalesced; j next -> 8 w-sharers inside block
    const int q  = tid % QW;
    const int jr = tid / QW;
    const int j  = jr % CPG;          // channel-in-group
    const int r  = jr / CPG;          // output row in tile
    const int h  = h0 + r;
    const int w0 = q * 4;

    const float hasLf = (q > 0) ? 1.f : 0.f;
    const float hasRf = (q < QW - 1) ? 1.f : 0.f;
    const int dL = (q > 0) ? -1 : 0;
    const int dR = (q < QW - 1) ? 4 : 3;   // clamped; zeroed by hasRf when invalid

    // ---------- front-batch the 9 per-pixel weight quads (long-latency) ----------
    const float* wbase = w + ((b * Gn + g) * 9) * HWn + h * Wn + w0;
    float4 wk[9];
#pragma unroll
    for (int k = 0; k < 9; ++k)
        wk[k] = *reinterpret_cast<const float4*>(wbase + k * HWn);

    // ---------- cooperative x staging: 8ch x 6 rows (h0-1..h0+4), zero-filled ----------
    {
        const int cb = (b * Cn + g) * HWn;
#pragma unroll
        for (int i = 0; i < 6; ++i) {
            int e = tid + i * BTH;            // 0..2687
            int jj  = e / (6 * Wn);
            int rem = e % (6 * Wn);
            int ri  = rem / Wn;
            int col = rem % Wn;
            int hh  = h0 - 1 + ri;
            float v = 0.f;
            if (hh >= 0 && hh < Hn)
                v = x[cb + jj * Gn * HWn + hh * Wn + col];
            sx[jj * JSTR + ri * Wn + col] = v;
        }
    }
    __syncthreads();

    // ---------- compute: x from smem, w from registers ----------
    const float* sj = sx + j * JSTR;
    float4 acc = make_float4(0.f, 0.f, 0.f, 0.f);
#pragma unroll
    for (int rr = 0; rr < 3; ++rr) {
        const float* srow = sj + (r + rr) * Wn;   // smem row h-1+rr (zero-filled if OOB)
        float4 c = *reinterpret_cast<const float4*>(srow + w0);
        float  l = srow[w0 + dL] * hasLf;
        float  rt = srow[w0 + dR] * hasRf;

        const float4 wk0 = wk[rr * 3 + 0];
        const float4 wk1 = wk[rr * 3 + 1];
        const float4 wk2 = wk[rr * 3 + 2];
        acc.x += l   * wk0.x + c.x * wk1.x + c.y * wk2.x;
        acc.y += c.x * wk0.y + c.y * wk1.y + c.z * wk2.y;
        acc.z += c.y * wk0.z + c.z * wk1.z + c.w * wk2.z;
        acc.w += c.z * wk0.w + c.w * wk1.w + rt  * wk2.w;
    }

    *reinterpret_cast<float4*>(out + (b * Cn + j * Gn + g) * HWn + h * Wn + w0) = acc;
}

extern "C" void kernel_launch(void* const* d_in, const int* in_sizes, int n_in,
                              void* d_out, int out_size) {
    const float* x = (const float*)d_in[0];   // (8,256,56,56)
    const float* w = (const float*)d_in[1];   // (8,32,9,56,56)
    float* out = (float*)d_out;               // (8,256,56,56)

    SKA_20950850470021_kernel<<<NBLK, BTH>>>(x, w, out);
}

// round 13
// speedup vs baseline: 1.7287x; 1.7287x over previous
#include <cuda_runtime.h>
#include <cuda_bf16.h>

#define Bn   8
#define Cn   256
#define Gn   32
#define CPG  8
#define Hn   56
#define Wn   56
#define HWn  3136          // 56*56
#define QW   14
#define ROWS 8             // output rows per block
#define BTH  224           // 14 q * 8 r * 2 jp
#define NBLK (Bn*Gn*(Hn/ROWS))   // 1792
#define CSTR 568           // smem channel stride in floats (10*56 + 8 pad)

__global__ __launch_bounds__(BTH, 3)
void SKA_20950850470021_kernel(const float* __restrict__ x,
                               const float* __restrict__ w,
                               float* __restrict__ out) {
    __shared__ float sx[CPG * CSTR];   // 18176 B: 8 ch x 10 rows x 56 (+pad)

    const int tid = threadIdx.x;
    const int bid = blockIdx.x;
    const int ht = bid % (Hn / ROWS);
    const int g  = (bid / (Hn / ROWS)) % Gn;
    const int b  = bid / ((Hn / ROWS) * Gn);
    const int h0 = ht * ROWS;

    const int q  = tid % QW;           // quad in row (lane-adjacent)
    const int rj = tid / QW;
    const int r  = rj % ROWS;          // output row in tile
    const int jp = rj / ROWS;          // 0..1 : which 4 channels
    const int h  = h0 + r;
    const int w0 = q * 4;
    const int lane = tid & 31;

    const int cb = (b * Cn + g) * HWn;

    // ---------- phase 1: batch the x-staging loads (5 float4 per thread) ----------
    float4 stg[5];
    int    sofs[5];
#pragma unroll
    for (int i = 0; i < 5; ++i) {
        int f   = i * BTH + tid;       // 0..1119 over 8ch x 10rows x 14quads
        int jj  = f / 140;
        int rem = f % 140;
        int ri  = rem / 14;            // smem row 0..9  (image row h0-1+ri)
        int c4  = rem % 14;
        int hh  = h0 - 1 + ri;
        float4 v = make_float4(0.f, 0.f, 0.f, 0.f);
        if (hh >= 0 && hh < Hn)
            v = *reinterpret_cast<const float4*>(x + cb + jj * (Gn * HWn) + hh * Wn + c4 * 4);
        stg[i]  = v;
        sofs[i] = jj * CSTR + ri * Wn + c4 * 4;
    }

    // ---------- phase 2: batch the 9 per-pixel weight quads ----------
    const float* wbase = w + ((b * Gn + g) * 9) * HWn + h * Wn + w0;
    float4 wk[9];
#pragma unroll
    for (int k = 0; k < 9; ++k)
        wk[k] = *reinterpret_cast<const float4*>(wbase + k * HWn);

    // ---------- phase 3: commit staging to smem ----------
#pragma unroll
    for (int i = 0; i < 5; ++i)
        *reinterpret_cast<float4*>(sx + sofs[i]) = stg[i];
    __syncthreads();

    // ---------- phase 4: compute (x from smem + shuffles, w from registers) ----------
    const float hasLf = (q > 0) ? 1.f : 0.f;
    const float hasRf = (q < QW - 1) ? 1.f : 0.f;
    const bool needL = (lane == 0)  && (q > 0);
    const bool needR = (lane == 31) && (q < QW - 1);

    float4 acc[4];
#pragma unroll
    for (int j = 0; j < 4; ++j) acc[j] = make_float4(0.f, 0.f, 0.f, 0.f);

#pragma unroll
    for (int j = 0; j < 4; ++j) {
        const float* sc = sx + (jp * 4 + j) * CSTR;
#pragma unroll
        for (int rr = 0; rr < 3; ++rr) {
            const float* srow = sc + (r + rr) * Wn;   // image row h-1+rr (zero-filled OOB)
            float4 c = *reinterpret_cast<const float4*>(srow + w0);
            float lv = __shfl_up_sync(0xFFFFFFFFu, c.w, 1);
            float rv = __shfl_down_sync(0xFFFFFFFFu, c.x, 1);
            if (needL) lv = srow[w0 - 1];
            if (needR) rv = srow[w0 + 4];
            lv *= hasLf;   // zeros image borders and cross-row shuffle garbage
            rv *= hasRf;

            const float4 wk0 = wk[rr * 3 + 0];
            const float4 wk1 = wk[rr * 3 + 1];
            const float4 wk2 = wk[rr * 3 + 2];
            acc[j].x += lv  * wk0.x + c.x * wk1.x + c.y * wk2.x;
            acc[j].y += c.x * wk0.y + c.y * wk1.y + c.z * wk2.y;
            acc[j].z += c.y * wk0.z + c.z * wk1.z + c.w * wk2.z;
            acc[j].w += c.z * wk0.w + c.w * wk1.w + rv  * wk2.w;
        }
    }

    // ---------- stores: 4 channels ----------
    const int obase = cb + h * Wn + w0;
#pragma unroll
    for (int j = 0; j < 4; ++j)
        *reinterpret_cast<float4*>(out + obase + (jp * 4 + j) * (Gn * HWn)) = acc[j];
}

extern "C" void kernel_launch(void* const* d_in, const int* in_sizes, int n_in,
                              void* d_out, int out_size) {
    const float* x = (const float*)d_in[0];   // (8,256,56,56)
    const float* w = (const float*)d_in[1];   // (8,32,9,56,56)
    float* out = (float*)d_out;               // (8,256,56,56)

    SKA_20950850470021_kernel<<<NBLK, BTH>>>(x, w, out);
}